// round 5
// baseline (speedup 1.0000x reference)
#include <cuda_runtime.h>
#include <cstdint>

#define M_MOL 64
#define N_ATM 512
#define RC2 49.0f      // (cutoff + shell)^2 = 7^2
#define I_TILE 8       // i's per block, split across 2 thread-groups
#define NTHREADS 256

__global__ __launch_bounds__(NTHREADS, 8) void nbl_kernel(
    const float* __restrict__ pos,   // [64, 512, 3]
    float* __restrict__ out)         // [64, 512, 512, 3]
{
    // SoA smem: conflict-free LDS.128 of 4 consecutive j
    __shared__ float sx[N_ATM], sy[N_ATM], sz[N_ATM];

    const int m = blockIdx.y;
    const float* pm = pos + (size_t)m * N_ATM * 3;

    // cooperative AoS -> SoA load (one-time, 1536 elements)
    for (int t = threadIdx.x; t < N_ATM * 3; t += NTHREADS) {
        const float v = pm[t];
        const int a = t / 3;
        const int c = t - 3 * a;
        if (c == 0)      sx[a] = v;
        else if (c == 1) sy[a] = v;
        else             sz[a] = v;
    }
    __syncthreads();

    const int tg = threadIdx.x >> 7;          // 0 or 1: i-group
    const int tj = threadIdx.x & 127;         // j-thread within group
    const int j0 = tj * 4;
    const int i_base = blockIdx.x * I_TILE + tg * (I_TILE / 2);

    float4* oblk = reinterpret_cast<float4*>(
        out + ((size_t)(m * N_ATM + i_base)) * N_ATM * 3) + tj * 3;

    #pragma unroll
    for (int ii = 0; ii < I_TILE / 2; ii++) {
        const int i = i_base + ii;
        // broadcast reads (all lanes in a warp hit the same address)
        const float xi = sx[i];
        const float yi = sy[i];
        const float zi = sz[i];

        // reload j positions each iteration (keeps live-register set small);
        // immediately turn them into displacements in place
        float4 dx = *reinterpret_cast<const float4*>(&sx[j0]);
        float4 dy = *reinterpret_cast<const float4*>(&sy[j0]);
        float4 dz = *reinterpret_cast<const float4*>(&sz[j0]);
        dx.x -= xi; dy.x -= yi; dz.x -= zi;
        dx.y -= xi; dy.y -= yi; dz.y -= zi;
        dx.z -= xi; dy.z -= yi; dz.z -= zi;
        dx.w -= xi; dy.w -= yi; dz.w -= zi;

        {
            const float d2 = dx.x * dx.x + dy.x * dy.x + dz.x * dz.x;
            if (!((d2 < RC2) && (j0 + 0 != i))) { dx.x = 0.f; dy.x = 0.f; dz.x = 0.f; }
        }
        {
            const float d2 = dx.y * dx.y + dy.y * dy.y + dz.y * dz.y;
            if (!((d2 < RC2) && (j0 + 1 != i))) { dx.y = 0.f; dy.y = 0.f; dz.y = 0.f; }
        }
        {
            const float d2 = dx.z * dx.z + dy.z * dy.z + dz.z * dz.z;
            if (!((d2 < RC2) && (j0 + 2 != i))) { dx.z = 0.f; dy.z = 0.f; dz.z = 0.f; }
        }
        {
            const float d2 = dx.w * dx.w + dy.w * dy.w + dz.w * dz.w;
            if (!((d2 < RC2) && (j0 + 3 != i))) { dx.w = 0.f; dy.w = 0.f; dz.w = 0.f; }
        }

        // pack 12 floats into 3 float4 and stream out (48B contiguous/thread)
        const float4 a = make_float4(dx.x, dy.x, dz.x, dx.y);
        const float4 b = make_float4(dy.y, dz.y, dx.z, dy.z);
        const float4 c = make_float4(dz.z, dx.w, dy.w, dz.w);

        float4* orow = oblk + (size_t)ii * (N_ATM * 3 / 4);
        __stcs(&orow[0], a);
        __stcs(&orow[1], b);
        __stcs(&orow[2], c);
    }
}

extern "C" void kernel_launch(void* const* d_in, const int* in_sizes, int n_in,
                              void* d_out, int out_size)
{
    const float* pos = (const float*)d_in[0];
    float* out = (float*)d_out;

    dim3 grid(N_ATM / I_TILE, M_MOL);   // (64, 64)
    nbl_kernel<<<grid, NTHREADS>>>(pos, out);
}